// round 1
// baseline (speedup 1.0000x reference)
#include <cuda_runtime.h>
#include <cstdint>
#include <cstddef>

namespace {
constexpr int kM = 64;
constexpr int kK = 4096;
constexpr int kN = 14336;
constexpr int kBN = 32;            // columns per block -> 448 blocks
constexpr int kBK = 128;           // one quant group per chunk
constexpr int kChunks = kK / kBK;  // 32
constexpr int kPad = 144;          // smem row stride in bytes (conflict-free mma loads)
constexpr int kThreads = 256;
}

// packed int8 activations [M, K] row-major (scratch: __device__ global, no mallocs)
__device__ __align__(16) int8_t g_x8[kM * kK];

__global__ void pack_x_kernel(const int* __restrict__ x) {
    int idx = blockIdx.x * blockDim.x + threadIdx.x;  // int4 index over M*K/4
    int4 v = __ldg(((const int4*)x) + idx);
    uint32_t w = (uint32_t)(v.x & 0xff) | ((uint32_t)(v.y & 0xff) << 8)
               | ((uint32_t)(v.z & 0xff) << 16) | ((uint32_t)(v.w & 0xff) << 24);
    ((uint32_t*)g_x8)[idx] = w;
}

__device__ __forceinline__ void cp_async16(uint32_t dst, const void* src) {
    asm volatile("cp.async.ca.shared.global [%0], [%1], 16;\n" :: "r"(dst), "l"(src));
}
__device__ __forceinline__ void cp_commit() { asm volatile("cp.async.commit_group;\n"); }
__device__ __forceinline__ void cp_wait_all() { asm volatile("cp.async.wait_group 0;\n" ::: "memory"); }

__device__ __forceinline__ void mma_s8(int c[4], uint32_t a0, uint32_t a1, uint32_t a2,
                                       uint32_t a3, uint32_t b0, uint32_t b1) {
    asm volatile(
        "mma.sync.aligned.m16n8k32.row.col.s32.s8.s8.s32 "
        "{%0,%1,%2,%3}, {%4,%5,%6,%7}, {%8,%9}, {%0,%1,%2,%3};\n"
        : "+r"(c[0]), "+r"(c[1]), "+r"(c[2]), "+r"(c[3])
        : "r"(a0), "r"(a1), "r"(a2), "r"(a3), "r"(b0), "r"(b1));
}

__global__ void __launch_bounds__(kThreads, 3)
w4a8_gemm_kernel(const int* __restrict__ qweight,
                 const int* __restrict__ s2_scales,
                 const int* __restrict__ s2_zeros,
                 const float* __restrict__ input_scales,
                 const float* __restrict__ s1_scales,
                 const float* __restrict__ bias,
                 float* __restrict__ out) {
    __shared__ __align__(16) int8_t As[2][kM * kPad];   // x tile, int8, padded rows
    __shared__ __align__(16) int8_t Bs[2][kBN * kPad];  // dequantized weights, int8

    const int t = threadIdx.x;
    const int warp = t >> 5;
    const int lane = t & 31;
    const int gq = lane >> 2;   // groupID (0..7)
    const int tg = lane & 3;    // threadID_in_group
    const int n0 = blockIdx.x * kBN;

    // ---------- producer mapping: thread -> (weight row, 16-int slice of chunk)
    const int nl = t >> 3;   // 0..31 local weight row
    const int t8 = t & 7;    // 0..7 slice within row
    const int n_glob = n0 + nl;
    const int4* qbase = ((const int4*)qweight) + (size_t)n_glob * (kK / 4);

    int4 qv[4];
    int s2r, zr;

    auto prefetch = [&](int c, int nb) {
        // A tile (64 x 128 int8) via cp.async: 512 x 16B transfers, 2 per thread
#pragma unroll
        for (int j = 0; j < 2; ++j) {
            int id = t + kThreads * j;
            int row = id >> 3, seg = id & 7;
            uint32_t dst = (uint32_t)__cvta_generic_to_shared(&As[nb][row * kPad + seg * 16]);
            const int8_t* src = g_x8 + row * kK + c * kBK + seg * 16;
            cp_async16(dst, src);
        }
        cp_commit();
        // raw q chunk: 16 int32 per thread, 4 x int4, streaming (no reuse)
#pragma unroll
        for (int j = 0; j < 4; ++j)
            qv[j] = __ldcs(qbase + c * (kBK / 4) + t8 * 4 + j);
        s2r = __ldg(s2_scales + c * kN + n_glob);
        zr  = __ldg(s2_zeros  + c * kN + n_glob);
    };

    auto dequant_sts = [&](int nb) {
        // w = q*s2 + zeros  in [-105,105] -> exact int8
        uint32_t w[4];
#pragma unroll
        for (int j = 0; j < 4; ++j) {
            int b0 = qv[j].x * s2r + zr;
            int b1 = qv[j].y * s2r + zr;
            int b2 = qv[j].z * s2r + zr;
            int b3 = qv[j].w * s2r + zr;
            w[j] = (uint32_t)(b0 & 0xff) | ((uint32_t)(b1 & 0xff) << 8)
                 | ((uint32_t)(b2 & 0xff) << 16) | ((uint32_t)(b3 & 0xff) << 24);
        }
        *(uint4*)(&Bs[nb][nl * kPad + t8 * 16]) = make_uint4(w[0], w[1], w[2], w[3]);
    };

    // ---------- consumer mapping: warp -> (m-tile, 2 n-tiles)
    const int mt = warp & 3;            // m-tile of 16 rows
    const int ntb = (warp >> 2) * 2;    // first of two 8-wide n-tiles
    int acc[2][4] = {};

    prefetch(0, 0);
    dequant_sts(0);
    cp_wait_all();
    __syncthreads();

    int buf = 0;
    for (int c = 0; c < kChunks; ++c) {
        if (c + 1 < kChunks) prefetch(c + 1, buf ^ 1);

        // 4 k-steps of m16n8k32 over the 128-wide chunk
#pragma unroll
        for (int ks = 0; ks < 4; ++ks) {
            const int8_t* ap = &As[buf][(mt * 16 + gq) * kPad + ks * 32 + tg * 4];
            uint32_t a0 = *(const uint32_t*)ap;
            uint32_t a2 = *(const uint32_t*)(ap + 16);
            uint32_t a1 = *(const uint32_t*)(ap + 8 * kPad);
            uint32_t a3 = *(const uint32_t*)(ap + 8 * kPad + 16);
#pragma unroll
            for (int i = 0; i < 2; ++i) {
                const int8_t* bp = &Bs[buf][((ntb + i) * 8 + gq) * kPad + ks * 32 + tg * 4];
                uint32_t b0 = *(const uint32_t*)bp;
                uint32_t b1 = *(const uint32_t*)(bp + 16);
                mma_s8(acc[i], a0, a1, a2, a3, b0, b1);
            }
        }

        if (c + 1 < kChunks) dequant_sts(buf ^ 1);
        cp_wait_all();
        __syncthreads();
        buf ^= 1;
    }

    // ---------- epilogue: out = acc * input_scales[m] * s1_scales[n] + bias[n]
    const int r0 = mt * 16 + gq;
    const float is0 = input_scales[r0];
    const float is1 = input_scales[r0 + 8];
#pragma unroll
    for (int i = 0; i < 2; ++i) {
        int n = n0 + (ntb + i) * 8 + tg * 2;
        float s1a = s1_scales[n], s1b = s1_scales[n + 1];
        float ba = bias[n], bb = bias[n + 1];
        float2 v0 = make_float2((float)acc[i][0] * is0 * s1a + ba,
                                (float)acc[i][1] * is0 * s1b + bb);
        float2 v1 = make_float2((float)acc[i][2] * is1 * s1a + ba,
                                (float)acc[i][3] * is1 * s1b + bb);
        *(float2*)(out + (size_t)r0 * kN + n) = v0;
        *(float2*)(out + (size_t)(r0 + 8) * kN + n) = v1;
    }
}

extern "C" void kernel_launch(void* const* d_in, const int* in_sizes, int n_in,
                              void* d_out, int out_size) {
    const int* x            = (const int*)d_in[0];
    const float* in_scales  = (const float*)d_in[1];
    // d_in[2] = input_sum (unused by the per-group kernel)
    const int* qweight      = (const int*)d_in[3];
    const int* s2_scales    = (const int*)d_in[4];
    const int* s2_zeros     = (const int*)d_in[5];
    const float* s1_scales  = (const float*)d_in[6];
    const float* bias       = (const float*)d_in[7];
    float* out              = (float*)d_out;
    (void)in_sizes; (void)n_in; (void)out_size;

    pack_x_kernel<<<(kM * kK / 4) / kThreads, kThreads>>>(x);
    w4a8_gemm_kernel<<<kN / kBN, kThreads>>>(qweight, s2_scales, s2_zeros,
                                             in_scales, s1_scales, bias, out);
}